// round 10
// baseline (speedup 1.0000x reference)
#include <cuda_runtime.h>
#include <cstdint>

// ---------------------------------------------------------------------------
// Causal flash attention, fp32 I/O, split-tf32 (hi/lo 3-term) tensor-core MMA.
// B=2, S=2048, H=16, D=128. Layout [B,S,H,D] for q,k,v,out.
// R10: occupancy fix from first measured profile (occ 12.3%, issue 50.7%,
// tensor 42%, dram 1.8% -> latency-bound). Changes vs R3:
//   - 2 CTAs/SM: smem 154.6KB -> 99.5KB (single-buffered K/V; sP deleted)
//   - P relayout C-frag -> A-frag via in-warp shfl (no smem round-trip)
//   - __launch_bounds__(NT, 2) to force <=128 regs
// Co-resident CTA now provides the latency hiding double-buffering used to.
// ---------------------------------------------------------------------------

#define DEV_INLINE __device__ __forceinline__

namespace fa {
constexpr int Bn = 2, Sn = 2048, Hn = 16, Dn = 128;
constexpr int BQ = 128;   // q rows per CTA
constexpr int BK = 32;    // keys per step
constexpr int NT = 256;   // threads per CTA (8 warps, 16 q-rows each)

constexpr int LDQ = Dn + 4;   // 132: A/K fragment banks = (4g+t), conflict-free
constexpr int LDK = Dn + 4;   // 132
constexpr int LDV = Dn + 8;   // 136: V fragment banks = (8t+g), conflict-free

constexpr int SQ_E = BQ * LDQ;        // 16896
constexpr int SK_E = BK * LDK;        // 4224 (single buffer)
constexpr int SV_E = BK * LDV;        // 4352 (single buffer)
constexpr int SMEM_FLOATS = SQ_E + SK_E + SV_E;              // 25472
constexpr size_t SMEM_BYTES = (size_t)SMEM_FLOATS * sizeof(float);  // 101,888 B
}  // namespace fa

DEV_INLINE uint32_t tf32_rna(float x) {
    uint32_t r;
    asm("cvt.rna.tf32.f32 %0, %1;" : "=r"(r) : "f"(x));
    return r;
}

DEV_INLINE float ex2f(float x) {
    float y;
    asm("ex2.approx.f32 %0, %1;" : "=f"(y) : "f"(x));
    return y;
}

DEV_INLINE void cp_async16(uint32_t smem_addr, const void* gptr) {
    asm volatile("cp.async.cg.shared.global [%0], [%1], 16;\n"
                 :: "r"(smem_addr), "l"(gptr));
}
DEV_INLINE void cp_commit() { asm volatile("cp.async.commit_group;\n"); }
template <int N>
DEV_INLINE void cp_wait() { asm volatile("cp.async.wait_group %0;\n" :: "n"(N)); }

// D = A(16x8) * B(8x8) + C, tf32 inputs (b32 containers), f32 accumulate.
// A row-major: a0=(g,t) a1=(g+8,t) a2=(g,t+4) a3=(g+8,t+4)
// B col-major: b0=(k=t,n=g) b1=(k=t+4,n=g)
// C: c0=(g,2t) c1=(g,2t+1) c2=(g+8,2t) c3=(g+8,2t+1)
DEV_INLINE void mma8(float c[4], const uint32_t a[4], uint32_t b0, uint32_t b1) {
    asm volatile(
        "mma.sync.aligned.m16n8k8.row.col.f32.tf32.tf32.f32 "
        "{%0,%1,%2,%3}, {%4,%5,%6,%7}, {%8,%9}, {%0,%1,%2,%3};\n"
        : "+f"(c[0]), "+f"(c[1]), "+f"(c[2]), "+f"(c[3])
        : "r"(a[0]), "r"(a[1]), "r"(a[2]), "r"(a[3]), "r"(b0), "r"(b1));
}

DEV_INLINE void split4(const float f[4], uint32_t hi[4], uint32_t lo[4]) {
#pragma unroll
    for (int x = 0; x < 4; ++x) {
        hi[x] = tf32_rna(f[x]);
        // residual fed raw: tf32 HW truncation of lo costs only ~2^-24 rel.
        lo[x] = __float_as_uint(f[x] - __uint_as_float(hi[x]));
    }
}

DEV_INLINE void split2(float f0, float f1, uint32_t& h0, uint32_t& h1,
                       uint32_t& l0, uint32_t& l1) {
    h0 = tf32_rna(f0);
    h1 = tf32_rna(f1);
    l0 = __float_as_uint(f0 - __uint_as_float(h0));
    l1 = __float_as_uint(f1 - __uint_as_float(h1));
}

__global__ __launch_bounds__(fa::NT, 2)
void fattn_tf32_kernel(const float* __restrict__ q, const float* __restrict__ k,
                       const float* __restrict__ v, float* __restrict__ out) {
    using namespace fa;
    extern __shared__ float smem[];
    float* sQ = smem;                   // [BQ][LDQ] fp32 (pre-scaled)
    float* sK = sQ + SQ_E;              // [BK][LDK] raw fp32 (single buffer)
    float* sV = sK + SK_E;              // [BK][LDV] raw fp32 (single buffer)

    const int b     = blockIdx.z;
    const int h     = blockIdx.y;
    const int qt    = (Sn / BQ - 1) - (int)blockIdx.x;  // heavy tiles first
    const int qbase = qt * BQ;
    const int tid   = threadIdx.x;
    const int warp  = tid >> 5;
    const int lane  = tid & 31;
    const int g     = lane >> 2;  // 0..7
    const int t     = lane & 3;   // 0..3
    const int wrow  = warp * 16;  // this warp's local q-row base

    const size_t row_stride = (size_t)Hn * Dn;  // stride between seq positions
    const float qscale = 1.4426950408889634f / sqrtf((float)Dn);  // log2(e)/sqrt(D)

    const float* kg0 = k + ((size_t)(b * Sn) * Hn + h) * Dn;
    const float* vg0 = v + ((size_t)(b * Sn) * Hn + h) * Dn;
    const int nsteps = (qbase + BQ) / BK;  // 4*(qt+1)

    // ---- stage Q (scaled, fp32); visible after first in-loop barrier ----
    {
        const float* qg = q + ((size_t)(b * Sn + qbase) * Hn + h) * Dn;
#pragma unroll
        for (int i = 0; i < (BQ * Dn / 4) / NT; ++i) {  // 16 float4 per thread
            int f4  = tid + i * NT;
            int row = f4 >> 5;
            int c4  = f4 & 31;
            float4 x = *reinterpret_cast<const float4*>(qg + (size_t)row * row_stride + c4 * 4);
            x.x *= qscale; x.y *= qscale; x.z *= qscale; x.w *= qscale;
            *reinterpret_cast<float4*>(&sQ[row * LDQ + c4 * 4]) = x;
        }
    }

    // accumulators
    float o[16][4];
#pragma unroll
    for (int j = 0; j < 16; ++j)
#pragma unroll
        for (int x = 0; x < 4; ++x) o[j][x] = 0.f;
    float m0 = -1e30f, m1 = -1e30f, l0 = 0.f, l1 = 0.f;

    for (int kt = 0; kt < nsteps; ++kt) {
        const int kbase = kt * BK;

        __syncthreads();   // all reads of previous tile done (and Q staged, kt=0)

        // stage tile kt (cp.async, single buffer); co-resident CTA hides latency
        {
#pragma unroll
            for (int i = 0; i < 4; ++i) {
                int f4 = tid + i * NT;
                int row = f4 >> 5, c4 = f4 & 31;
                const float* kp = kg0 + (size_t)(kbase + row) * row_stride + c4 * 4;
                const float* vp = vg0 + (size_t)(kbase + row) * row_stride + c4 * 4;
                cp_async16((uint32_t)__cvta_generic_to_shared(&sK[row * LDK + c4 * 4]), kp);
                cp_async16((uint32_t)__cvta_generic_to_shared(&sV[row * LDV + c4 * 4]), vp);
            }
            cp_commit();
            cp_wait<0>();
        }
        __syncthreads();   // tile kt visible to all warps

        // per-warp causal skip: all of this warp's rows above the key band
        if (qbase + wrow + 15 >= kbase) {
            // ---- S = Q K^T (split-tf32, 3 terms) ----
            float sc[4][4];
#pragma unroll
            for (int j = 0; j < 4; ++j)
#pragma unroll
                for (int x = 0; x < 4; ++x) sc[j][x] = 0.f;

#pragma unroll
            for (int kc = 0; kc < Dn / 8; ++kc) {  // 16 chunks over d
                const int d0 = kc * 8;
                float af[4];
                af[0] = sQ[(wrow + g) * LDQ + d0 + t];
                af[1] = sQ[(wrow + g + 8) * LDQ + d0 + t];
                af[2] = sQ[(wrow + g) * LDQ + d0 + t + 4];
                af[3] = sQ[(wrow + g + 8) * LDQ + d0 + t + 4];
                uint32_t ah[4], al[4];
                split4(af, ah, al);
#pragma unroll
                for (int jn = 0; jn < 4; ++jn) {  // 8 key-cols per n-tile
                    const int n0 = jn * 8;
                    float bf0 = sK[(n0 + g) * LDK + d0 + t];
                    float bf1 = sK[(n0 + g) * LDK + d0 + t + 4];
                    uint32_t bh0, bh1, bl0, bl1;
                    split2(bf0, bf1, bh0, bh1, bl0, bl1);
                    mma8(sc[jn], ah, bh0, bh1);
                    mma8(sc[jn], ah, bl0, bl1);
                    mma8(sc[jn], al, bh0, bh1);
                }
            }

            // ---- causal mask (diagonal band only) ----
            const int qg0 = qbase + wrow + g;
            const int qg1 = qg0 + 8;
            if (kbase + BK - 1 > qbase + wrow) {
#pragma unroll
                for (int jn = 0; jn < 4; ++jn) {
                    int kgc = kbase + jn * 8 + 2 * t;
                    if (kgc     > qg0) sc[jn][0] = -1e30f;
                    if (kgc + 1 > qg0) sc[jn][1] = -1e30f;
                    if (kgc     > qg1) sc[jn][2] = -1e30f;
                    if (kgc + 1 > qg1) sc[jn][3] = -1e30f;
                }
            }

            // ---- online softmax (rows g and g+8; reduce over 4 t-lanes) ----
            float tm0 = -1e30f, tm1 = -1e30f;
#pragma unroll
            for (int jn = 0; jn < 4; ++jn) {
                tm0 = fmaxf(tm0, fmaxf(sc[jn][0], sc[jn][1]));
                tm1 = fmaxf(tm1, fmaxf(sc[jn][2], sc[jn][3]));
            }
            tm0 = fmaxf(tm0, __shfl_xor_sync(0xffffffffu, tm0, 1));
            tm0 = fmaxf(tm0, __shfl_xor_sync(0xffffffffu, tm0, 2));
            tm1 = fmaxf(tm1, __shfl_xor_sync(0xffffffffu, tm1, 1));
            tm1 = fmaxf(tm1, __shfl_xor_sync(0xffffffffu, tm1, 2));
            const float mn0 = fmaxf(m0, tm0);
            const float mn1 = fmaxf(m1, tm1);
            const float c0 = ex2f(m0 - mn0);
            const float c1 = ex2f(m1 - mn1);
            m0 = mn0; m1 = mn1;

            float rs0 = 0.f, rs1 = 0.f;
#pragma unroll
            for (int jn = 0; jn < 4; ++jn) {
                sc[jn][0] = ex2f(sc[jn][0] - mn0);
                sc[jn][1] = ex2f(sc[jn][1] - mn0);
                sc[jn][2] = ex2f(sc[jn][2] - mn1);
                sc[jn][3] = ex2f(sc[jn][3] - mn1);
                rs0 += sc[jn][0] + sc[jn][1];
                rs1 += sc[jn][2] + sc[jn][3];
            }
            rs0 += __shfl_xor_sync(0xffffffffu, rs0, 1);
            rs0 += __shfl_xor_sync(0xffffffffu, rs0, 2);
            rs1 += __shfl_xor_sync(0xffffffffu, rs1, 1);
            rs1 += __shfl_xor_sync(0xffffffffu, rs1, 2);
            l0 = l0 * c0 + rs0;
            l1 = l1 * c1 + rs1;

            // rescale O accumulators
#pragma unroll
            for (int jn = 0; jn < 16; ++jn) {
                o[jn][0] *= c0; o[jn][1] *= c0;
                o[jn][2] *= c1; o[jn][3] *= c1;
            }

            // ---- O += P V (split-tf32, 3 terms); P relayout via shfl ----
            // C-frag of sc[kc] holds P[g][8kc+2t(+1)], P[g+8][...]. The A-frag
            // value P[g][8kc+t] lives in lane 4g+(t>>1) as sc[kc][t&1]; the
            // t+4 column in lane 4g+(t>>1)+2. Rows g+8 come from sc[kc][2|3].
#pragma unroll
            for (int kc = 0; kc < BK / 8; ++kc) {  // 4 chunks over keys
                const int kk0 = kc * 8;
                const int s  = 4 * g + (t >> 1);
                const int s2 = s + 2;
                const bool odd = (t & 1) != 0;
                float x00 = __shfl_sync(0xffffffffu, sc[kc][0], s);
                float x01 = __shfl_sync(0xffffffffu, sc[kc][1], s);
                float x10 = __shfl_sync(0xffffffffu, sc[kc][2], s);
                float x11 = __shfl_sync(0xffffffffu, sc[kc][3], s);
                float y00 = __shfl_sync(0xffffffffu, sc[kc][0], s2);
                float y01 = __shfl_sync(0xffffffffu, sc[kc][1], s2);
                float y10 = __shfl_sync(0xffffffffu, sc[kc][2], s2);
                float y11 = __shfl_sync(0xffffffffu, sc[kc][3], s2);
                float af[4];
                af[0] = odd ? x01 : x00;   // P[g    ][kk0+t]
                af[1] = odd ? x11 : x10;   // P[g+8  ][kk0+t]
                af[2] = odd ? y01 : y00;   // P[g    ][kk0+t+4]
                af[3] = odd ? y11 : y10;   // P[g+8  ][kk0+t+4]
                uint32_t ah[4], al[4];
                split4(af, ah, al);
#pragma unroll
                for (int jn = 0; jn < 16; ++jn) {  // 8 d-cols per n-tile
                    const int n0 = jn * 8;
                    float bf0 = sV[(kk0 + t) * LDV + n0 + g];
                    float bf1 = sV[(kk0 + t + 4) * LDV + n0 + g];
                    uint32_t bh0, bh1, bl0, bl1;
                    split2(bf0, bf1, bh0, bh1, bl0, bl1);
                    mma8(o[jn], ah, bh0, bh1);
                    mma8(o[jn], ah, bl0, bl1);
                    mma8(o[jn], al, bh0, bh1);
                }
            }
        }
    }

    // ---- epilogue: normalize + store ----
    const float inv0 = 1.f / l0;
    const float inv1 = 1.f / l1;
    const int qg0 = qbase + wrow + g;
    const int qg1 = qg0 + 8;
    float* o0 = out + ((size_t)(b * Sn + qg0) * Hn + h) * Dn;
    float* o1 = out + ((size_t)(b * Sn + qg1) * Hn + h) * Dn;
#pragma unroll
    for (int jn = 0; jn < 16; ++jn) {
        const int d0 = jn * 8 + 2 * t;
        *reinterpret_cast<float2*>(&o0[d0]) = make_float2(o[jn][0] * inv0, o[jn][1] * inv0);
        *reinterpret_cast<float2*>(&o1[d0]) = make_float2(o[jn][2] * inv1, o[jn][3] * inv1);
    }
}

extern "C" void kernel_launch(void* const* d_in, const int* in_sizes, int n_in,
                              void* d_out, int out_size) {
    (void)in_sizes; (void)n_in; (void)out_size;
    const float* q = (const float*)d_in[0];
    const float* k = (const float*)d_in[1];
    const float* v = (const float*)d_in[2];
    float* out = (float*)d_out;

    cudaFuncSetAttribute(fattn_tf32_kernel,
                         cudaFuncAttributeMaxDynamicSharedMemorySize,
                         (int)fa::SMEM_BYTES);
    dim3 grid(fa::Sn / fa::BQ, fa::Hn, fa::Bn);  // (16, 16, 2) = 512 CTAs
    fattn_tf32_kernel<<<grid, fa::NT, fa::SMEM_BYTES>>>(q, k, v, out);
}

// round 12
// speedup vs baseline: 1.2741x; 1.2741x over previous
#include <cuda_runtime.h>
#include <cstdint>

// ---------------------------------------------------------------------------
// Causal flash attention, fp32 I/O, split-tf32 tensor-core MMA.
// B=2, S=2048, H=16, D=128. Layout [B,S,H,D] for q,k,v,out.
// R12 == R11 (broker timeout; candidate still unbenched). vs measured-best R9:
//   (1) QK accumulator split 3-way (hh/hl/lh) -> RAW chain depth 48 -> 16
//   (2) 2-term PV (drop P_lo*V term): -17% MMA; predicted rel_err ~1e-4
//   (3) shfl P relayout (verified correct in R10's passing run), sP deleted
// R10 lessons pinned: no 128-reg cap (spills), keep double-buffered cp.async.
// ---------------------------------------------------------------------------

#define DEV_INLINE __device__ __forceinline__

namespace fa {
constexpr int Bn = 2, Sn = 2048, Hn = 16, Dn = 128;
constexpr int BQ = 128;   // q rows per CTA
constexpr int BK = 32;    // keys per step
constexpr int NT = 256;   // threads per CTA (8 warps, 16 q-rows each)

constexpr int LDQ = Dn + 4;   // 132: A/K fragment banks = (4g+t), conflict-free
constexpr int LDK = Dn + 4;   // 132
constexpr int LDV = Dn + 8;   // 136: V fragment banks = (8t+g), conflict-free

constexpr int SQ_E = BQ * LDQ;        // 16896
constexpr int SK_E = BK * LDK;        // 4224 (per buffer)
constexpr int SV_E = BK * LDV;        // 4352 (per buffer)
constexpr int SMEM_FLOATS = SQ_E + 2 * SK_E + 2 * SV_E;      // 34048
constexpr size_t SMEM_BYTES = (size_t)SMEM_FLOATS * sizeof(float);  // 136,192 B
}  // namespace fa

DEV_INLINE uint32_t tf32_rna(float x) {
    uint32_t r;
    asm("cvt.rna.tf32.f32 %0, %1;" : "=r"(r) : "f"(x));
    return r;
}

DEV_INLINE float ex2f(float x) {
    float y;
    asm("ex2.approx.f32 %0, %1;" : "=f"(y) : "f"(x));
    return y;
}

DEV_INLINE void cp_async16(uint32_t smem_addr, const void* gptr) {
    asm volatile("cp.async.cg.shared.global [%0], [%1], 16;\n"
                 :: "r"(smem_addr), "l"(gptr));
}
DEV_INLINE void cp_commit() { asm volatile("cp.async.commit_group;\n"); }
template <int N>
DEV_INLINE void cp_wait() { asm volatile("cp.async.wait_group %0;\n" :: "n"(N)); }

// D = A(16x8) * B(8x8) + C, tf32 inputs (b32 containers), f32 accumulate.
// A row-major: a0=(g,t) a1=(g+8,t) a2=(g,t+4) a3=(g+8,t+4)
// B col-major: b0=(k=t,n=g) b1=(k=t+4,n=g)
// C: c0=(g,2t) c1=(g,2t+1) c2=(g+8,2t) c3=(g+8,2t+1)
DEV_INLINE void mma8(float c[4], const uint32_t a[4], uint32_t b0, uint32_t b1) {
    asm volatile(
        "mma.sync.aligned.m16n8k8.row.col.f32.tf32.tf32.f32 "
        "{%0,%1,%2,%3}, {%4,%5,%6,%7}, {%8,%9}, {%0,%1,%2,%3};\n"
        : "+f"(c[0]), "+f"(c[1]), "+f"(c[2]), "+f"(c[3])
        : "r"(a[0]), "r"(a[1]), "r"(a[2]), "r"(a[3]), "r"(b0), "r"(b1));
}

DEV_INLINE void split4(const float f[4], uint32_t hi[4], uint32_t lo[4]) {
#pragma unroll
    for (int x = 0; x < 4; ++x) {
        hi[x] = tf32_rna(f[x]);
        lo[x] = __float_as_uint(f[x] - __uint_as_float(hi[x]));
    }
}

DEV_INLINE void split2(float f0, float f1, uint32_t& h0, uint32_t& h1,
                       uint32_t& l0, uint32_t& l1) {
    h0 = tf32_rna(f0);
    h1 = tf32_rna(f1);
    l0 = __float_as_uint(f0 - __uint_as_float(h0));
    l1 = __float_as_uint(f1 - __uint_as_float(h1));
}

__global__ __launch_bounds__(fa::NT, 1)
void fattn_tf32_kernel(const float* __restrict__ q, const float* __restrict__ k,
                       const float* __restrict__ v, float* __restrict__ out) {
    using namespace fa;
    extern __shared__ float smem[];
    float* sQ = smem;                   // [BQ][LDQ] fp32 (pre-scaled)
    float* sK = sQ + SQ_E;              // 2 x [BK][LDK] raw fp32 (double buffer)
    float* sV = sK + 2 * SK_E;          // 2 x [BK][LDV] raw fp32

    const int b     = blockIdx.z;
    const int h     = blockIdx.y;
    const int qt    = (Sn / BQ - 1) - (int)blockIdx.x;  // heavy tiles first
    const int qbase = qt * BQ;
    const int tid   = threadIdx.x;
    const int warp  = tid >> 5;
    const int lane  = tid & 31;
    const int g     = lane >> 2;  // 0..7
    const int t     = lane & 3;   // 0..3
    const int wrow  = warp * 16;  // this warp's local q-row base

    const size_t row_stride = (size_t)Hn * Dn;  // stride between seq positions
    const float qscale = 1.4426950408889634f / sqrtf((float)Dn);  // log2(e)/sqrt(D)

    const float* kg0 = k + ((size_t)(b * Sn) * Hn + h) * Dn;
    const float* vg0 = v + ((size_t)(b * Sn) * Hn + h) * Dn;
    const int nsteps = (qbase + BQ) / BK;  // 4*(qt+1)

    // ---- kick off tile 0 (cp.async) ----
    {
#pragma unroll
        for (int i = 0; i < 4; ++i) {
            int f4 = tid + i * NT;
            int row = f4 >> 5, c4 = f4 & 31;
            const float* kp = kg0 + (size_t)row * row_stride + c4 * 4;
            const float* vp = vg0 + (size_t)row * row_stride + c4 * 4;
            cp_async16((uint32_t)__cvta_generic_to_shared(&sK[row * LDK + c4 * 4]), kp);
            cp_async16((uint32_t)__cvta_generic_to_shared(&sV[row * LDV + c4 * 4]), vp);
        }
        cp_commit();
    }

    // ---- stage Q (scaled, fp32) while tile 0 is in flight ----
    {
        const float* qg = q + ((size_t)(b * Sn + qbase) * Hn + h) * Dn;
#pragma unroll
        for (int i = 0; i < (BQ * Dn / 4) / NT; ++i) {  // 16 float4 per thread
            int f4  = tid + i * NT;
            int row = f4 >> 5;
            int c4  = f4 & 31;
            float4 x = *reinterpret_cast<const float4*>(qg + (size_t)row * row_stride + c4 * 4);
            x.x *= qscale; x.y *= qscale; x.z *= qscale; x.w *= qscale;
            *reinterpret_cast<float4*>(&sQ[row * LDQ + c4 * 4]) = x;
        }
    }

    // accumulators
    float o[16][4];
#pragma unroll
    for (int j = 0; j < 16; ++j)
#pragma unroll
        for (int x = 0; x < 4; ++x) o[j][x] = 0.f;
    float m0 = -1e30f, m1 = -1e30f, l0 = 0.f, l1 = 0.f;

    for (int kt = 0; kt < nsteps; ++kt) {
        const int kbase = kt * BK;
        const int cur = kt & 1;
        float* cK = sK + cur * SK_E;
        float* cV = sV + cur * SV_E;

        cp_wait<0>();
        __syncthreads();   // tile kt visible; prior reads of other buffer done

        // prefetch tile kt+1 into the other buffer (lands during compute)
        if (kt + 1 < nsteps) {
            const int nb = kbase + BK;
            float* nK = sK + (1 - cur) * SK_E;
            float* nV = sV + (1 - cur) * SV_E;
#pragma unroll
            for (int i = 0; i < 4; ++i) {
                int f4 = tid + i * NT;
                int row = f4 >> 5, c4 = f4 & 31;
                const float* kp = kg0 + (size_t)(nb + row) * row_stride + c4 * 4;
                const float* vp = vg0 + (size_t)(nb + row) * row_stride + c4 * 4;
                cp_async16((uint32_t)__cvta_generic_to_shared(&nK[row * LDK + c4 * 4]), kp);
                cp_async16((uint32_t)__cvta_generic_to_shared(&nV[row * LDV + c4 * 4]), vp);
            }
            cp_commit();
        }

        // per-warp causal skip
        if (qbase + wrow + 15 >= kbase) {
            // ---- S = Q K^T (split-tf32, 3 terms, 3 independent accumulators) ----
            float scA[4][4], scB[4][4], scC[4][4];
#pragma unroll
            for (int j = 0; j < 4; ++j)
#pragma unroll
                for (int x = 0; x < 4; ++x) { scA[j][x] = 0.f; scB[j][x] = 0.f; scC[j][x] = 0.f; }

#pragma unroll
            for (int kc = 0; kc < Dn / 8; ++kc) {  // 16 chunks over d
                const int d0 = kc * 8;
                float af[4];
                af[0] = sQ[(wrow + g) * LDQ + d0 + t];
                af[1] = sQ[(wrow + g + 8) * LDQ + d0 + t];
                af[2] = sQ[(wrow + g) * LDQ + d0 + t + 4];
                af[3] = sQ[(wrow + g + 8) * LDQ + d0 + t + 4];
                uint32_t ah[4], al[4];
                split4(af, ah, al);
#pragma unroll
                for (int jn = 0; jn < 4; ++jn) {  // 8 key-cols per n-tile
                    const int n0 = jn * 8;
                    float bf0 = cK[(n0 + g) * LDK + d0 + t];
                    float bf1 = cK[(n0 + g) * LDK + d0 + t + 4];
                    uint32_t bh0, bh1, bl0, bl1;
                    split2(bf0, bf1, bh0, bh1, bl0, bl1);
                    mma8(scA[jn], ah, bh0, bh1);   // hh chain (depth 16)
                    mma8(scB[jn], ah, bl0, bl1);   // hl chain (depth 16)
                    mma8(scC[jn], al, bh0, bh1);   // lh chain (depth 16)
                }
            }
            // merge the three partial accumulators
            float sc[4][4];
#pragma unroll
            for (int jn = 0; jn < 4; ++jn)
#pragma unroll
                for (int x = 0; x < 4; ++x)
                    sc[jn][x] = (scA[jn][x] + scB[jn][x]) + scC[jn][x];

            // ---- causal mask (diagonal band only) ----
            const int qg0 = qbase + wrow + g;
            const int qg1 = qg0 + 8;
            if (kbase + BK - 1 > qbase + wrow) {
#pragma unroll
                for (int jn = 0; jn < 4; ++jn) {
                    int kgc = kbase + jn * 8 + 2 * t;
                    if (kgc     > qg0) sc[jn][0] = -1e30f;
                    if (kgc + 1 > qg0) sc[jn][1] = -1e30f;
                    if (kgc     > qg1) sc[jn][2] = -1e30f;
                    if (kgc + 1 > qg1) sc[jn][3] = -1e30f;
                }
            }

            // ---- online softmax (rows g and g+8; reduce over 4 t-lanes) ----
            float tm0 = -1e30f, tm1 = -1e30f;
#pragma unroll
            for (int jn = 0; jn < 4; ++jn) {
                tm0 = fmaxf(tm0, fmaxf(sc[jn][0], sc[jn][1]));
                tm1 = fmaxf(tm1, fmaxf(sc[jn][2], sc[jn][3]));
            }
            tm0 = fmaxf(tm0, __shfl_xor_sync(0xffffffffu, tm0, 1));
            tm0 = fmaxf(tm0, __shfl_xor_sync(0xffffffffu, tm0, 2));
            tm1 = fmaxf(tm1, __shfl_xor_sync(0xffffffffu, tm1, 1));
            tm1 = fmaxf(tm1, __shfl_xor_sync(0xffffffffu, tm1, 2));
            const float mn0 = fmaxf(m0, tm0);
            const float mn1 = fmaxf(m1, tm1);
            const float c0 = ex2f(m0 - mn0);
            const float c1 = ex2f(m1 - mn1);
            m0 = mn0; m1 = mn1;

            float rs0 = 0.f, rs1 = 0.f;
#pragma unroll
            for (int jn = 0; jn < 4; ++jn) {
                sc[jn][0] = ex2f(sc[jn][0] - mn0);
                sc[jn][1] = ex2f(sc[jn][1] - mn0);
                sc[jn][2] = ex2f(sc[jn][2] - mn1);
                sc[jn][3] = ex2f(sc[jn][3] - mn1);
                rs0 += sc[jn][0] + sc[jn][1];
                rs1 += sc[jn][2] + sc[jn][3];
            }
            rs0 += __shfl_xor_sync(0xffffffffu, rs0, 1);
            rs0 += __shfl_xor_sync(0xffffffffu, rs0, 2);
            rs1 += __shfl_xor_sync(0xffffffffu, rs1, 1);
            rs1 += __shfl_xor_sync(0xffffffffu, rs1, 2);
            l0 = l0 * c0 + rs0;
            l1 = l1 * c1 + rs1;

            // rescale O accumulators
#pragma unroll
            for (int jn = 0; jn < 16; ++jn) {
                o[jn][0] *= c0; o[jn][1] *= c0;
                o[jn][2] *= c1; o[jn][3] *= c1;
            }

            // ---- O += P V (2-term: P_hi*V_hi + P_hi*V_lo); shfl P relayout ----
            // A-frag value P[g][8kc+t] lives in lane 4g+(t>>1) as sc[kc][t&1];
            // column t+4 in lane 4g+(t>>1)+2; rows g+8 from sc[kc][2|3].
#pragma unroll
            for (int kc = 0; kc < BK / 8; ++kc) {  // 4 chunks over keys
                const int kk0 = kc * 8;
                const int s  = 4 * g + (t >> 1);
                const int s2 = s + 2;
                const bool odd = (t & 1) != 0;
                float x00 = __shfl_sync(0xffffffffu, sc[kc][0], s);
                float x01 = __shfl_sync(0xffffffffu, sc[kc][1], s);
                float x10 = __shfl_sync(0xffffffffu, sc[kc][2], s);
                float x11 = __shfl_sync(0xffffffffu, sc[kc][3], s);
                float y00 = __shfl_sync(0xffffffffu, sc[kc][0], s2);
                float y01 = __shfl_sync(0xffffffffu, sc[kc][1], s2);
                float y10 = __shfl_sync(0xffffffffu, sc[kc][2], s2);
                float y11 = __shfl_sync(0xffffffffu, sc[kc][3], s2);
                uint32_t ah[4];
                ah[0] = tf32_rna(odd ? x01 : x00);   // P[g  ][kk0+t]
                ah[1] = tf32_rna(odd ? x11 : x10);   // P[g+8][kk0+t]
                ah[2] = tf32_rna(odd ? y01 : y00);   // P[g  ][kk0+t+4]
                ah[3] = tf32_rna(odd ? y11 : y10);   // P[g+8][kk0+t+4]
#pragma unroll
                for (int jn = 0; jn < 16; ++jn) {  // 8 d-cols per n-tile
                    const int n0 = jn * 8;
                    float bf0 = cV[(kk0 + t) * LDV + n0 + g];
                    float bf1 = cV[(kk0 + t + 4) * LDV + n0 + g];
                    uint32_t bh0, bh1, bl0, bl1;
                    split2(bf0, bf1, bh0, bh1, bl0, bl1);
                    mma8(o[jn], ah, bh0, bh1);
                    mma8(o[jn], ah, bl0, bl1);
                }
            }
        }
    }

    // ---- epilogue: normalize + store ----
    const float inv0 = 1.f / l0;
    const float inv1 = 1.f / l1;
    const int qg0 = qbase + wrow + g;
    const int qg1 = qg0 + 8;
    float* o0 = out + ((size_t)(b * Sn + qg0) * Hn + h) * Dn;
    float* o1 = out + ((size_t)(b * Sn + qg1) * Hn + h) * Dn;
#pragma unroll
    for (int jn = 0; jn < 16; ++jn) {
        const int d0 = jn * 8 + 2 * t;
        *reinterpret_cast<float2*>(&o0[d0]) = make_float2(o[jn][0] * inv0, o[jn][1] * inv0);
        *reinterpret_cast<float2*>(&o1[d0]) = make_float2(o[jn][2] * inv1, o[jn][3] * inv1);
    }
}

extern "C" void kernel_launch(void* const* d_in, const int* in_sizes, int n_in,
                              void* d_out, int out_size) {
    (void)in_sizes; (void)n_in; (void)out_size;
    const float* q = (const float*)d_in[0];
    const float* k = (const float*)d_in[1];
    const float* v = (const float*)d_in[2];
    float* out = (float*)d_out;

    cudaFuncSetAttribute(fattn_tf32_kernel,
                         cudaFuncAttributeMaxDynamicSharedMemorySize,
                         (int)fa::SMEM_BYTES);
    dim3 grid(fa::Sn / fa::BQ, fa::Hn, fa::Bn);  // (16, 16, 2) = 512 CTAs
    fattn_tf32_kernel<<<grid, fa::NT, fa::SMEM_BYTES>>>(q, k, v, out);
}